// round 14
// baseline (speedup 1.0000x reference)
#include <cuda_runtime.h>
#include <cstdint>

// MultiScaleDeformableAttention — GB300
// value:              (8, 22223, 8, 32)  float32
// sampling_locations: (8, 900, 8, 4, 4, 2) float32
// attention_weights:  (8, 900, 8, 4, 4) float32
// out:                (8, 900, 256) float32
//
// R13 winner (148 pinned+helper CTAs, 3-tier cache policy) with Phase A
// computed ONCE per task: lane s (=lane&15) owns descriptor set
// (lvl,pt) = (s>>2, s&3) -> 4 offsets + 4 folded weights in 8 regs.
// Phase B redistributes them with __shfl_sync (8 shfls/level) and keeps the
// tiered LDG.128 gather:
//   lvl-0  : __ldcs  (stream)   lvl-1 : __ldcg (L2, skip L1)
//   lvl-2/3: __ldg   (L1-resident per pinned (b,h))
// Saves ~3x the Phase-A issue slots and ~24 descriptor regs vs R13.

#define BS  8
#define NQ  900
#define NH  8
#define DC  32
#define NL  4
#define NPT 4
#define NKEYS 22223
#define KS4 (NH * DC / 4)        // float4s per key = 64
#define QHALF (NQ / 2)           // 450
#define QMAIN 396                // queries handled by the pinned CTA
#define QREST (QHALF - QMAIN)    // 54 leftover per (bh,half)
#define NEXTRA 20                // helper CTAs
#define TOTREST (128 * QREST)    // 6912 leftover tasks
#define FULLM 0xffffffffu

__device__ __forceinline__ void process_task(
    int task,
    const float4* __restrict__ v4,       // value base for (b,h) + cp
    const float2* __restrict__ loc2,
    const float*  __restrict__ aw,
    float* __restrict__ out,
    int lane, int g, int cp)
{
    // ---------- Phase A (single pass): lane s owns set (lvl,pt) ----------
    int   o00, o10, o01, o11;
    float w00, w10, w01, w11;
    {
        const int s   = lane & 15;            // lanes 16-31 duplicate
        const int W     = (s < 4) ? 167 : (s < 8) ? 84    : (s < 12) ? 42    : 21;
        const int H     = (s < 4) ? 100 : (s < 8) ? 50    : (s < 12) ? 25    : 13;
        const int start = (s < 4) ? 0   : (s < 8) ? 16700 : (s < 12) ? 20900 : 21950;

        const int li = task * (NL * NPT) + s;
        const float2 l2 = __ldcs(loc2 + li);
        const float  w  = __ldcs(aw + li);

        const float x = l2.x * (float)W - 0.5f;
        const float y = l2.y * (float)H - 0.5f;
        const float xf = floorf(x);
        const float yf = floorf(y);
        const int x0 = (int)xf;
        const int y0 = (int)yf;
        const int x1 = x0 + 1;
        const int y1 = y0 + 1;

        float wx1 = x - xf;
        float wx0 = 1.0f - wx1;
        float wy1 = y - yf;
        float wy0 = 1.0f - wy1;

        // branch-free OOB: clamp index, zero the edge weight
        if (x0 < 0 || x0 > W - 1) wx0 = 0.0f;
        if (x1 < 0 || x1 > W - 1) wx1 = 0.0f;
        if (y0 < 0 || y0 > H - 1) wy0 = 0.0f;
        if (y1 < 0 || y1 > H - 1) wy1 = 0.0f;
        const int x0c = min(max(x0, 0), W - 1);
        const int x1c = min(max(x1, 0), W - 1);
        const int y0c = min(max(y0, 0), H - 1);
        const int y1c = min(max(y1, 0), H - 1);

        w00 = w * wx0 * wy0;
        w10 = w * wx1 * wy0;
        w01 = w * wx0 * wy1;
        w11 = w * wx1 * wy1;

        const int r0 = start + y0c * W;
        const int r1 = start + y1c * W;
        o00 = (r0 + x0c) * KS4;
        o10 = (r0 + x1c) * KS4;
        o01 = (r1 + x0c) * KS4;
        o11 = (r1 + x1c) * KS4;
    }

    // ---------- Phase B: shfl-distribute + tiered LDG.128 gather ----------
    float4 acc = make_float4(0.f, 0.f, 0.f, 0.f);

    #pragma unroll
    for (int lvl = 0; lvl < NL; ++lvl) {
        const int src = lvl * NPT + g;       // owning lane of set (lvl, g)
        const int   a0 = __shfl_sync(FULLM, o00, src);
        const int   a1 = __shfl_sync(FULLM, o10, src);
        const int   a2 = __shfl_sync(FULLM, o01, src);
        const int   a3 = __shfl_sync(FULLM, o11, src);
        const float b0 = __shfl_sync(FULLM, w00, src);
        const float b1 = __shfl_sync(FULLM, w10, src);
        const float b2 = __shfl_sync(FULLM, w01, src);
        const float b3 = __shfl_sync(FULLM, w11, src);

        float4 a, c, d, e;
        if (lvl == 0) {
            a = __ldcs(v4 + a0);  c = __ldcs(v4 + a1);
            d = __ldcs(v4 + a2);  e = __ldcs(v4 + a3);
        } else if (lvl == 1) {
            a = __ldcg(v4 + a0);  c = __ldcg(v4 + a1);
            d = __ldcg(v4 + a2);  e = __ldcg(v4 + a3);
        } else {
            a = __ldg(v4 + a0);   c = __ldg(v4 + a1);
            d = __ldg(v4 + a2);   e = __ldg(v4 + a3);
        }

        acc.x += a.x * b0 + c.x * b1 + d.x * b2 + e.x * b3;
        acc.y += a.y * b0 + c.y * b1 + d.y * b2 + e.y * b3;
        acc.z += a.z * b0 + c.z * b1 + d.z * b2 + e.z * b3;
        acc.w += a.w * b0 + c.w * b1 + d.w * b2 + e.w * b3;
    }

    // reduce the 4 point-groups (lanes cp, cp+8, cp+16, cp+24)
    #pragma unroll
    for (int m = 8; m <= 16; m <<= 1) {
        acc.x += __shfl_xor_sync(FULLM, acc.x, m);
        acc.y += __shfl_xor_sync(FULLM, acc.y, m);
        acc.z += __shfl_xor_sync(FULLM, acc.z, m);
        acc.w += __shfl_xor_sync(FULLM, acc.w, m);
    }

    if (g == 0) {
        ((float4*)out)[(size_t)task * (DC / 4) + cp] = acc;
    }
}

__global__ __launch_bounds__(1024, 1) void msda_kernel(
    const float* __restrict__ value,
    const float* __restrict__ loc,
    const float* __restrict__ aw,
    float* __restrict__ out)
{
    const int cid  = blockIdx.x;
    const int tid  = threadIdx.x;
    const int wid  = tid >> 5;
    const int lane = tid & 31;
    const int g  = lane >> 3;            // point within level (0..3)
    const int cp = lane & 7;             // channel quad (0..7)

    const float4* __restrict__ val4 = (const float4*)value;
    const float2* __restrict__ loc2 = (const float2*)loc;

    if (cid < 128) {
        // pinned CTA: one (b,h,half), queries [0, QMAIN)
        const int bh   = cid >> 1;
        const int half = cid & 1;
        const int b    = bh >> 3;
        const int h    = bh & (NH - 1);

        const float4* __restrict__ v4 =
            val4 + ((size_t)(b * NKEYS) * NH + h) * (DC / 4) + cp;

        for (int ql = wid; ql < QMAIN; ql += 32) {
            const int q    = half * QHALF + ql;
            const int task = (b * NQ + q) * NH + h;
            process_task(task, v4, loc2, aw, out, lane, g, cp);
        }
    } else {
        // helper CTA: strided sweep over the leftover tasks
        const int j = cid - 128;         // 0..19
        for (int idx = wid; ; idx += 32) {
            const int t = j + idx * NEXTRA;      // flat leftover index
            if (t >= TOTREST) break;

            const int bhh  = t / QREST;          // (bh,half) id 0..127
            const int rem  = t - bhh * QREST;    // 0..53
            const int bh   = bhh >> 1;
            const int half = bhh & 1;
            const int b    = bh >> 3;
            const int h    = bh & (NH - 1);

            const int q    = half * QHALF + QMAIN + rem;
            const int task = (b * NQ + q) * NH + h;

            const float4* __restrict__ v4 =
                val4 + ((size_t)(b * NKEYS) * NH + h) * (DC / 4) + cp;
            process_task(task, v4, loc2, aw, out, lane, g, cp);
        }
    }
}

extern "C" void kernel_launch(void* const* d_in, const int* in_sizes, int n_in,
                              void* d_out, int out_size)
{
    const float* value = (const float*)d_in[0];
    const float* loc   = (const float*)d_in[1];
    const float* aw    = (const float*)d_in[2];
    float* out         = (float*)d_out;

    // 128 pinned CTAs + 20 helper CTAs = 148 = one per SM
    msda_kernel<<<148, 1024>>>(value, loc, aw, out);
}